// round 13
// baseline (speedup 1.0000x reference)
#include <cuda_runtime.h>
#include <math.h>
#include <stdint.h>

// ---------------------------------------------------------------------------
// LSTM_88716844466217 : B=64, ILEN=256, TLEN=64 (T=320), IDIM=512, HDIM=1024,
// ODIM=128. fp32, packed fma.rn.f32x2.
// R13: TLP round — both big kernels were running 2-4 warps/SMSP and are
// latency-bound (ncu: fma 26%, issue 25%, occ 12.6%).
//   xproj:   BM64/TM4, 3 CTAs/SM -> 6 warps/SMSP.
//   persist: 1024 threads, 8-way K-split -> 8 warps/SMSP. Barrier unchanged.
// ---------------------------------------------------------------------------

constexpr int BSZ  = 64;
constexpr int ILEN = 256;
constexpr int TLEN = 64;
constexpr int TT   = ILEN + TLEN;   // 320
constexpr int IDIM = 512;
constexpr int HDIM = 1024;
constexpr int G4   = 4 * HDIM;      // 4096
constexpr int ODIM = 128;
constexpr int NBLK = 128;           // persistent blocks (1/SM, all resident)

// Scratch (device globals: allocation-free per harness rules)
__device__ float g_xproj[(size_t)BSZ * ILEN * G4];   // [b*ILEN+t][4096], bias included
__device__ float g_h0[BSZ * HDIM];
__device__ float g_h1[BSZ * HDIM];
__device__ float g_hs[(size_t)TLEN * BSZ * HDIM];    // h for t in [ILEN, TT)
__device__ unsigned g_arrive;                         // grid barrier counter

#define DINL __device__ __forceinline__

DINL void ffma2(unsigned long long &d, unsigned long long a, unsigned long long b) {
    asm("fma.rn.f32x2 %0, %1, %2, %0;" : "+l"(d) : "l"(a), "l"(b));
}
DINL float pair_sum(unsigned long long v) {
    return __uint_as_float((unsigned)(v & 0xffffffffu)) +
           __uint_as_float((unsigned)(v >> 32));
}
DINL float sigmoidf_(float x) { return 1.0f / (1.0f + __expf(-x)); }

DINL void cp_async16(uint32_t saddr, const float* gptr) {
    asm volatile("cp.async.cg.shared.global [%0], [%1], 16;" :: "r"(saddr), "l"(gptr));
}
DINL void cp_commit() { asm volatile("cp.async.commit_group;"); }
template<int N> DINL void cp_wait() { asm volatile("cp.async.wait_group %0;" :: "n"(N)); }

// LDS.64 (k-pair) MAC: low register footprint, good for high-occupancy tiles.
// A rows: tr + RSI*i (i<TM), B rows: tc + CSJ*j (j<TN), NP pairs of 2 k each.
template<int TM, int TN, int NP, int AST, int BST, int RSI, int CSJ>
DINL void mac64(const float* __restrict__ Ap, const float* __restrict__ Bp,
                int tr, int tc, unsigned long long (&acc)[TM][TN]) {
#pragma unroll
    for (int p = 0; p < NP; ++p) {
        unsigned long long a[TM], b[TN];
#pragma unroll
        for (int i = 0; i < TM; ++i)
            a[i] = *reinterpret_cast<const unsigned long long*>(Ap + (tr + RSI * i) * AST + 2 * p);
#pragma unroll
        for (int j = 0; j < TN; ++j)
            b[j] = *reinterpret_cast<const unsigned long long*>(Bp + (tc + CSJ * j) * BST + 2 * p);
#pragma unroll
        for (int i = 0; i < TM; ++i)
#pragma unroll
            for (int j = 0; j < TN; ++j)
                ffma2(acc[i][j], a[i], b[j]);
    }
}

// LDS.128 quad MAC (clf only, unchanged).
template<int TM, int TN, int NQ, int AST, int BST, int RSI, int CSJ>
DINL void mac_g(const float* __restrict__ Ap, const float* __restrict__ Bp,
                int tr, int tc, unsigned long long (&acc)[TM][TN]) {
#pragma unroll
    for (int q = 0; q < NQ; ++q) {
        ulonglong2 a[TM], b[TN];
#pragma unroll
        for (int i = 0; i < TM; ++i)
            a[i] = *reinterpret_cast<const ulonglong2*>(Ap + (tr + RSI * i) * AST + q * 4);
#pragma unroll
        for (int j = 0; j < TN; ++j)
            b[j] = *reinterpret_cast<const ulonglong2*>(Bp + (tc + CSJ * j) * BST + q * 4);
#pragma unroll
        for (int i = 0; i < TM; ++i)
#pragma unroll
            for (int j = 0; j < TN; ++j) {
                ffma2(acc[i][j], a[i].x, b[j].x);
                ffma2(acc[i][j], a[i].y, b[j].y);
            }
    }
}

// ---------------------------------------------------------------------------
// init: zero h(t=0) and barrier counter
// ---------------------------------------------------------------------------
__global__ void init_kernel() {
    int i = blockIdx.x * blockDim.x + threadIdx.x;
    if (i < BSZ * HDIM) g_h0[i] = 0.0f;
    if (i == 0) g_arrive = 0u;
}

// ---------------------------------------------------------------------------
// x_proj GEMM: C[16384,4096] = inp[16384,512] @ w_ih[4096,512]^T + bias
// BM=64, BN=64, KC=32, 256 thr, TM=4, TN=4. 3 CTAs/SM (6 warps/SMSP).
// 3-buffer cp.async pipeline, ONE syncthreads per K-tile.
// Epilogue staged through smem for coalesced STG.128.
// ---------------------------------------------------------------------------
constexpr int XP_SKC   = 36;                       // 32+4, bank-safe, 16B rows
constexpr int XP_ABUF  = 64 * XP_SKC;              // 2304 floats
constexpr int XP_BBUF  = 64 * XP_SKC;              // 2304 floats
constexpr int XP_NT    = IDIM / 32;                // 16 K-tiles
constexpr int XP_CST   = 68;                       // epilogue stage stride (64+4)
constexpr size_t XP_SMEM = (size_t)(3 * XP_ABUF + 3 * XP_BBUF) * 4;  // 55296 B
// epilogue stage needs 64*68 = 4352 floats <= 3*XP_ABUF = 6912  (overlay ok)

__global__ __launch_bounds__(256, 3) void xproj_kernel(const float* __restrict__ inp,
                                                       const float* __restrict__ w_ih,
                                                       const float* __restrict__ bias) {
    extern __shared__ float sm[];
    float* As = sm;                    // [3][64][36]
    float* Bs = sm + 3 * XP_ABUF;      // [3][64][36]

    const int tid = threadIdx.x;
    const int tr = tid >> 4, tc = tid & 15;
    const int row0 = blockIdx.y * 64;
    const int col0 = blockIdx.x * 64;
    const uint32_t sa = (uint32_t)__cvta_generic_to_shared(As);
    const uint32_t sb = (uint32_t)__cvta_generic_to_shared(Bs);

    unsigned long long acc[4][4];
#pragma unroll
    for (int i = 0; i < 4; ++i)
#pragma unroll
        for (int j = 0; j < 4; ++j) acc[i][j] = 0ull;

    auto issue = [&](int kt, int buf) {
#pragma unroll
        for (int v = 0; v < 2; ++v) {              // A: 512 float4
            int id = tid + v * 256;
            int r = id >> 3, kq = id & 7;
            cp_async16(sa + (uint32_t)((buf * XP_ABUF + r * XP_SKC + kq * 4) * 4),
                       inp + (size_t)(row0 + r) * IDIM + kt * 32 + kq * 4);
        }
#pragma unroll
        for (int v = 0; v < 2; ++v) {              // B: 512 float4
            int id = tid + v * 256;
            int r = id >> 3, kq = id & 7;
            cp_async16(sb + (uint32_t)((buf * XP_BBUF + r * XP_SKC + kq * 4) * 4),
                       w_ih + (size_t)(col0 + r) * IDIM + kt * 32 + kq * 4);
        }
    };

    issue(0, 0); cp_commit();
    issue(1, 1); cp_commit();

    for (int kt = 0; kt < XP_NT; ++kt) {
        // pending real groups here: {kt, kt+1} (no empty commits anywhere)
        if (kt < XP_NT - 1) cp_wait<1>(); else cp_wait<0>();
        __syncthreads();                 // buffer kt ready; all warps done mac(kt-1)
        if (kt + 2 < XP_NT) { issue(kt + 2, (kt + 2) % 3); cp_commit(); }
        int buf = kt % 3;
        mac64<4, 4, 16, XP_SKC, XP_SKC, 16, 16>(As + buf * XP_ABUF, Bs + buf * XP_BBUF,
                                                tr, tc, acc);
    }

    // ---- epilogue: stage tile in smem, store coalesced ----
    __syncthreads();                     // all mac done; As free for staging
    float* Cs = As;                      // [64][68]
#pragma unroll
    for (int j = 0; j < 4; ++j) {
        float bv = bias[col0 + tc + 16 * j];
#pragma unroll
        for (int i = 0; i < 4; ++i)
            Cs[(tr + 16 * i) * XP_CST + tc + 16 * j] = pair_sum(acc[i][j]) + bv;
    }
    __syncthreads();
#pragma unroll
    for (int v = 0; v < 4; ++v) {        // 64 rows x 16 float4 = 1024 stores
        int id = tid + v * 256;
        int r = id >> 4, c4 = id & 15;
        *reinterpret_cast<float4*>(g_xproj + (size_t)(row0 + r) * G4 + col0 + c4 * 4) =
            *reinterpret_cast<const float4*>(Cs + r * XP_CST + c4 * 4);
    }
}

// ---------------------------------------------------------------------------
// Persistent recurrent kernel. 128 blocks x 1024 threads (8 warps/SMSP).
// Block bx owns hidden cols [bx*8, bx*8+8) across all 4 gates (32 w_hh rows),
// cached in SMEM for all 320 steps. 8-way K-split: eighth q = tid>>7 owns
// k subrange q*16..q*16+16 per 128-wide chunk; TM=4 x TN=4 per thread
// (LDS.64 operands -> ~52 live regs under the 64-reg cap at occ 1).
// h streamed per step via cp.async: 8 chunks of 128 k, 2 buffers,
// one syncthreads per chunk. c lives in a register (threads 0..511).
// Inter-block sync: R8-proven global barrier, UNCHANGED.
// ---------------------------------------------------------------------------
constexpr int WS_STRIDE = 1028;                    // 1024+4 words
constexpr int WS_SIZE   = 32 * WS_STRIDE;          // 32896 floats (131584 B)
constexpr int AS_STRIDE = 132;                     // 128+4 words (16B-aligned rows)
constexpr int AS_CHUNK  = 64 * AS_STRIDE;          // 8448 floats per buffer
constexpr int AS_SIZE   = 2 * AS_CHUNK;            // 16896 floats (67584 B)
constexpr int GB_HALF   = 64 * 33;                 // 2112 floats
// Gb (8 x 2112 = 16896 floats) overlays the As buffers EXACTLY (sync-separated).
constexpr size_t LP_SMEM = (size_t)(WS_SIZE + AS_SIZE) * 4;       // 199168 B

__global__ __launch_bounds__(1024, 1) void lstm_persist(const float* __restrict__ w_hh,
                                                        const float* __restrict__ bias) {
    extern __shared__ float sm[];
    float* Ws = sm;                    // [32][1028]
    float* As = sm + WS_SIZE;          // [2][64][132]
    float* Gb = As;                    // overlay, [8][64][33]

    const int tid  = threadIdx.x;
    const int q    = tid >> 7;         // K-split eighth 0..7
    const int htid = tid & 127;
    const int tc   = htid & 7;         // local col base 0..7
    const int tr   = htid >> 3;        // batch row base 0..15
    const int j0   = blockIdx.x * 8;

    // pointwise mapping (threads 0..511 only; fixed across steps -> c in reg)
    const int pb = tid >> 3;           // batch 0..63 (valid for tid<512)
    const int pj = tid & 7;            // hidden col offset 0..7
    float c_reg = 0.0f;

    // ---- one-time: cache this block's 32 w_hh rows (full K) in SMEM ----
    for (int i = tid; i < 32 * 256; i += 1024) {       // 8192 float4
        int row = i >> 8, qq = i & 255;
        int grow = (row >> 3) * HDIM + j0 + (row & 7); // gate*H + j0 + jj
        *reinterpret_cast<float4*>(Ws + row * WS_STRIDE + qq * 4) =
            *reinterpret_cast<const float4*>(w_hh + (size_t)grow * HDIM + qq * 4);
    }
    const uint32_t as_base = (uint32_t)__cvta_generic_to_shared(As);
    __syncthreads();

    for (int t = 0; t < TT; ++t) {
        const float* __restrict__ hin = (t & 1) ? g_h1 : g_h0;
        float* __restrict__ hout      = (t & 1) ? g_h0 : g_h1;

        // prefetch x_proj gate values (consumed ~8us later -> latency hidden)
        float xg[4];
        if (tid < 512) {
            const float* xr = (t < ILEN) ? (g_xproj + ((size_t)pb * ILEN + t) * G4) : bias;
#pragma unroll
            for (int g = 0; g < 4; ++g) xg[g] = __ldg(xr + g * HDIM + j0 + pj);
        }

        unsigned long long acc[4][4];
#pragma unroll
        for (int i = 0; i < 4; ++i)
#pragma unroll
            for (int j = 0; j < 4; ++j) acc[i][j] = 0ull;

        // h chunk streamer: 64 batch rows x 128 k  (2048 float4, 2/thread)
        auto issue = [&](int c, int buf) {
#pragma unroll
            for (int v = 0; v < 2; ++v) {
                int id = tid + v * 1024;
                int r = id >> 5, q32 = id & 31;
                cp_async16(as_base + (uint32_t)((buf * AS_CHUNK + r * AS_STRIDE + q32 * 4) * 4),
                           hin + (size_t)r * HDIM + c * 128 + q32 * 4);
            }
        };

        issue(0, 0); cp_commit();

        for (int c = 0; c < 8; ++c) {
            cp_wait<0>();                // chunk c (sole pending group) complete
            __syncthreads();             // all warps done mac(c-1): buf (c+1)&1 free
            if (c < 7) { issue(c + 1, (c + 1) & 1); cp_commit(); }
            const float* Ap = As + (c & 1) * AS_CHUNK + q * 16;
            const float* Wp = Ws + c * 128 + q * 16;
            mac64<4, 4, 8, AS_STRIDE, WS_STRIDE, 16, 8>(Ap, Wp, tr, tc, acc);
        }
        __syncthreads();                 // all mac done before Gb overlays As

        // dump K-split partials: Gb[q][batch][lcol], stride 33
        float* gb = Gb + q * GB_HALF;
#pragma unroll
        for (int i = 0; i < 4; ++i)
#pragma unroll
            for (int j = 0; j < 4; ++j)
                gb[(tr + 16 * i) * 33 + (tc + 8 * j)] = pair_sum(acc[i][j]);
        __syncthreads();

        // pointwise LSTM update: 512 elements, threads 0..511
        if (tid < 512) {
            float pre[4];
#pragma unroll
            for (int g = 0; g < 4; ++g) {
                int off = pb * 33 + g * 8 + pj;
                float s = xg[g];
#pragma unroll
                for (int qq = 0; qq < 8; ++qq) s += Gb[qq * GB_HALF + off];
                pre[g] = s;
            }
            float ig = sigmoidf_(pre[0]);
            float fg = sigmoidf_(pre[1]);
            float gg = tanhf(pre[2]);
            float og = sigmoidf_(pre[3]);
            float cn = fg * c_reg + ig * gg;
            c_reg = cn;
            float hn = og * tanhf(cn);
            int hidx = pb * HDIM + j0 + pj;
            hout[hidx] = hn;
            if (t >= ILEN)
                g_hs[(size_t)(t - ILEN) * (BSZ * HDIM) + hidx] = hn;
        }

        // ---- grid barrier (R8-proven protocol, verbatim) ----
        __threadfence();
        __syncthreads();
        if (tid == 0) {
            atomicAdd(&g_arrive, 1u);
            unsigned target = (unsigned)NBLK * (unsigned)(t + 1);
            while (*(volatile unsigned*)&g_arrive < target) { }
        }
        __syncthreads();
        __threadfence();
    }
}

// ---------------------------------------------------------------------------
// classifier: out[b][tt][o] = sigmoid(hs_row . clf_w[o] + clf_b[o])
// rows = tt*64 + b. BM=64, BN=64, KC=64 (16 quads), TM=4, TN=4, stride 68.
// ---------------------------------------------------------------------------
__global__ __launch_bounds__(256) void clf_kernel(const float* __restrict__ clf_w,
                                                  const float* __restrict__ clf_b,
                                                  float* __restrict__ out) {
    constexpr int KC = 64, SKC = 68, TM = 4, TN = 4;
    __shared__ float As[64 * SKC];
    __shared__ float Bs[64 * SKC];
    const int tid = threadIdx.x;
    const int tr = tid >> 4, tc = tid & 15;
    const int row0 = blockIdx.y * 64;
    const int col0 = blockIdx.x * 64;

    unsigned long long acc[TM][TN];
#pragma unroll
    for (int i = 0; i < TM; ++i)
#pragma unroll
        for (int j = 0; j < TN; ++j) acc[i][j] = 0ull;

    for (int k0 = 0; k0 < HDIM; k0 += KC) {
#pragma unroll
        for (int v = 0; v < 4; ++v) {           // 64*16 = 1024 float4
            int id = tid + v * 256;
            int r = id >> 4, kq = id & 15;
            *reinterpret_cast<float4*>(As + r * SKC + kq * 4) =
                *reinterpret_cast<const float4*>(g_hs + (size_t)(row0 + r) * HDIM + k0 + kq * 4);
        }
#pragma unroll
        for (int v = 0; v < 4; ++v) {
            int id = tid + v * 256;
            int r = id >> 4, kq = id & 15;
            *reinterpret_cast<float4*>(Bs + r * SKC + kq * 4) =
                *reinterpret_cast<const float4*>(clf_w + (size_t)(col0 + r) * HDIM + k0 + kq * 4);
        }
        __syncthreads();
        mac_g<TM, TN, KC / 4, SKC, SKC, 16, 16>(As, Bs, tr, tc, acc);
        __syncthreads();
    }

#pragma unroll
    for (int j = 0; j < TN; ++j) {
        int o = col0 + tc + 16 * j;
        float bv = clf_b[o];
#pragma unroll
        for (int i = 0; i < TM; ++i) {
            int r  = row0 + tr + 16 * i;
            int tt = r >> 6;
            int b  = r & 63;
            out[((size_t)b * TLEN + tt) * ODIM + o] =
                1.0f / (1.0f + expf(-(pair_sum(acc[i][j]) + bv)));
        }
    }
}

// ---------------------------------------------------------------------------
// launch (graph-capturable: kernel launches only, default stream)
// Inputs (metadata order): inp, tlen, w_ih, w_hh, b, clf_w, clf_b
// ---------------------------------------------------------------------------
extern "C" void kernel_launch(void* const* d_in, const int* in_sizes, int n_in,
                              void* d_out, int out_size) {
    const float* inp   = (const float*)d_in[0];
    // d_in[1] = tlen (int32) — fixed at 64
    const float* w_ih  = (const float*)d_in[2];
    const float* w_hh  = (const float*)d_in[3];
    const float* bias  = (const float*)d_in[4];
    const float* clf_w = (const float*)d_in[5];
    const float* clf_b = (const float*)d_in[6];
    float* out = (float*)d_out;

    cudaFuncSetAttribute(xproj_kernel, cudaFuncAttributeMaxDynamicSharedMemorySize,
                         (int)XP_SMEM);
    cudaFuncSetAttribute(lstm_persist, cudaFuncAttributeMaxDynamicSharedMemorySize,
                         (int)LP_SMEM);

    init_kernel<<<(BSZ * HDIM + 255) / 256, 256>>>();
    xproj_kernel<<<dim3(G4 / 64, (BSZ * ILEN) / 64), 256, XP_SMEM>>>(inp, w_ih, bias);
    lstm_persist<<<NBLK, 1024, LP_SMEM>>>(w_hh, bias);
    clf_kernel<<<dim3(ODIM / 64, (TLEN * BSZ) / 64), 256>>>(clf_w, clf_b, out);
}

// round 14
// speedup vs baseline: 1.3517x; 1.3517x over previous
#include <cuda_runtime.h>
#include <math.h>
#include <stdint.h>

// ---------------------------------------------------------------------------
// LSTM_88716844466217 : B=64, ILEN=256, TLEN=64 (T=320), IDIM=512, HDIM=1024,
// ODIM=128. fp32, packed fma.rn.f32x2.
// R14: recombination round.
//   persist = R12 verbatim (512 thr, LDS.128 mac, no spills, proven barrier).
//   xproj   = R13 version (BM64, TM4xTN4, 3 CTAs/SM = 6 warps/SMSP, ~60 regs).
// Tests the TLP theory on xproj alone; persist regression (spills) undone.
// ---------------------------------------------------------------------------

constexpr int BSZ  = 64;
constexpr int ILEN = 256;
constexpr int TLEN = 64;
constexpr int TT   = ILEN + TLEN;   // 320
constexpr int IDIM = 512;
constexpr int HDIM = 1024;
constexpr int G4   = 4 * HDIM;      // 4096
constexpr int ODIM = 128;
constexpr int NBLK = 128;           // persistent blocks (1/SM, all resident)

// Scratch (device globals: allocation-free per harness rules)
__device__ float g_xproj[(size_t)BSZ * ILEN * G4];   // [b*ILEN+t][4096], bias included
__device__ float g_h0[BSZ * HDIM];
__device__ float g_h1[BSZ * HDIM];
__device__ float g_hs[(size_t)TLEN * BSZ * HDIM];    // h for t in [ILEN, TT)
__device__ unsigned g_arrive;                         // grid barrier counter

#define DINL __device__ __forceinline__

DINL void ffma2(unsigned long long &d, unsigned long long a, unsigned long long b) {
    asm("fma.rn.f32x2 %0, %1, %2, %0;" : "+l"(d) : "l"(a), "l"(b));
}
DINL float pair_sum(unsigned long long v) {
    return __uint_as_float((unsigned)(v & 0xffffffffu)) +
           __uint_as_float((unsigned)(v >> 32));
}
DINL float sigmoidf_(float x) { return 1.0f / (1.0f + __expf(-x)); }

DINL void cp_async16(uint32_t saddr, const float* gptr) {
    asm volatile("cp.async.cg.shared.global [%0], [%1], 16;" :: "r"(saddr), "l"(gptr));
}
DINL void cp_commit() { asm volatile("cp.async.commit_group;"); }
template<int N> DINL void cp_wait() { asm volatile("cp.async.wait_group %0;" :: "n"(N)); }

// LDS.64 (k-pair) MAC: low register footprint (xproj @ 3 CTAs/SM).
template<int TM, int TN, int NP, int AST, int BST, int RSI, int CSJ>
DINL void mac64(const float* __restrict__ Ap, const float* __restrict__ Bp,
                int tr, int tc, unsigned long long (&acc)[TM][TN]) {
#pragma unroll
    for (int p = 0; p < NP; ++p) {
        unsigned long long a[TM], b[TN];
#pragma unroll
        for (int i = 0; i < TM; ++i)
            a[i] = *reinterpret_cast<const unsigned long long*>(Ap + (tr + RSI * i) * AST + 2 * p);
#pragma unroll
        for (int j = 0; j < TN; ++j)
            b[j] = *reinterpret_cast<const unsigned long long*>(Bp + (tc + CSJ * j) * BST + 2 * p);
#pragma unroll
        for (int i = 0; i < TM; ++i)
#pragma unroll
            for (int j = 0; j < TN; ++j)
                ffma2(acc[i][j], a[i], b[j]);
    }
}

// LDS.128 quad MAC (persist + clf).
template<int TM, int TN, int NQ, int AST, int BST, int RSI, int CSJ>
DINL void mac_g(const float* __restrict__ Ap, const float* __restrict__ Bp,
                int tr, int tc, unsigned long long (&acc)[TM][TN]) {
#pragma unroll
    for (int q = 0; q < NQ; ++q) {
        ulonglong2 a[TM], b[TN];
#pragma unroll
        for (int i = 0; i < TM; ++i)
            a[i] = *reinterpret_cast<const ulonglong2*>(Ap + (tr + RSI * i) * AST + q * 4);
#pragma unroll
        for (int j = 0; j < TN; ++j)
            b[j] = *reinterpret_cast<const ulonglong2*>(Bp + (tc + CSJ * j) * BST + q * 4);
#pragma unroll
        for (int i = 0; i < TM; ++i)
#pragma unroll
            for (int j = 0; j < TN; ++j) {
                ffma2(acc[i][j], a[i].x, b[j].x);
                ffma2(acc[i][j], a[i].y, b[j].y);
            }
    }
}

// ---------------------------------------------------------------------------
// init: zero h(t=0) and barrier counter
// ---------------------------------------------------------------------------
__global__ void init_kernel() {
    int i = blockIdx.x * blockDim.x + threadIdx.x;
    if (i < BSZ * HDIM) g_h0[i] = 0.0f;
    if (i == 0) g_arrive = 0u;
}

// ---------------------------------------------------------------------------
// x_proj GEMM: C[16384,4096] = inp[16384,512] @ w_ih[4096,512]^T + bias
// BM=64, BN=64, KC=32, 256 thr, TM=4, TN=4. 3 CTAs/SM (6 warps/SMSP).
// 3-buffer cp.async pipeline, ONE syncthreads per K-tile.
// Epilogue staged through smem for coalesced STG.128.   (R13 version)
// ---------------------------------------------------------------------------
constexpr int XP_SKC   = 36;                       // 32+4, bank-safe, 16B rows
constexpr int XP_ABUF  = 64 * XP_SKC;              // 2304 floats
constexpr int XP_BBUF  = 64 * XP_SKC;              // 2304 floats
constexpr int XP_NT    = IDIM / 32;                // 16 K-tiles
constexpr int XP_CST   = 68;                       // epilogue stage stride (64+4)
constexpr size_t XP_SMEM = (size_t)(3 * XP_ABUF + 3 * XP_BBUF) * 4;  // 55296 B
// epilogue stage needs 64*68 = 4352 floats <= 3*XP_ABUF = 6912  (overlay ok)

__global__ __launch_bounds__(256, 3) void xproj_kernel(const float* __restrict__ inp,
                                                       const float* __restrict__ w_ih,
                                                       const float* __restrict__ bias) {
    extern __shared__ float sm[];
    float* As = sm;                    // [3][64][36]
    float* Bs = sm + 3 * XP_ABUF;      // [3][64][36]

    const int tid = threadIdx.x;
    const int tr = tid >> 4, tc = tid & 15;
    const int row0 = blockIdx.y * 64;
    const int col0 = blockIdx.x * 64;
    const uint32_t sa = (uint32_t)__cvta_generic_to_shared(As);
    const uint32_t sb = (uint32_t)__cvta_generic_to_shared(Bs);

    unsigned long long acc[4][4];
#pragma unroll
    for (int i = 0; i < 4; ++i)
#pragma unroll
        for (int j = 0; j < 4; ++j) acc[i][j] = 0ull;

    auto issue = [&](int kt, int buf) {
#pragma unroll
        for (int v = 0; v < 2; ++v) {              // A: 512 float4
            int id = tid + v * 256;
            int r = id >> 3, kq = id & 7;
            cp_async16(sa + (uint32_t)((buf * XP_ABUF + r * XP_SKC + kq * 4) * 4),
                       inp + (size_t)(row0 + r) * IDIM + kt * 32 + kq * 4);
        }
#pragma unroll
        for (int v = 0; v < 2; ++v) {              // B: 512 float4
            int id = tid + v * 256;
            int r = id >> 3, kq = id & 7;
            cp_async16(sb + (uint32_t)((buf * XP_BBUF + r * XP_SKC + kq * 4) * 4),
                       w_ih + (size_t)(col0 + r) * IDIM + kt * 32 + kq * 4);
        }
    };

    issue(0, 0); cp_commit();
    issue(1, 1); cp_commit();

    for (int kt = 0; kt < XP_NT; ++kt) {
        // pending real groups here: {kt, kt+1} (no empty commits anywhere)
        if (kt < XP_NT - 1) cp_wait<1>(); else cp_wait<0>();
        __syncthreads();                 // buffer kt ready; all warps done mac(kt-1)
        if (kt + 2 < XP_NT) { issue(kt + 2, (kt + 2) % 3); cp_commit(); }
        int buf = kt % 3;
        mac64<4, 4, 16, XP_SKC, XP_SKC, 16, 16>(As + buf * XP_ABUF, Bs + buf * XP_BBUF,
                                                tr, tc, acc);
    }

    // ---- epilogue: stage tile in smem, store coalesced ----
    __syncthreads();                     // all mac done; As free for staging
    float* Cs = As;                      // [64][68]
#pragma unroll
    for (int j = 0; j < 4; ++j) {
        float bv = bias[col0 + tc + 16 * j];
#pragma unroll
        for (int i = 0; i < 4; ++i)
            Cs[(tr + 16 * i) * XP_CST + tc + 16 * j] = pair_sum(acc[i][j]) + bv;
    }
    __syncthreads();
#pragma unroll
    for (int v = 0; v < 4; ++v) {        // 64 rows x 16 float4 = 1024 stores
        int id = tid + v * 256;
        int r = id >> 4, c4 = id & 15;
        *reinterpret_cast<float4*>(g_xproj + (size_t)(row0 + r) * G4 + col0 + c4 * 4) =
            *reinterpret_cast<const float4*>(Cs + r * XP_CST + c4 * 4);
    }
}

// ---------------------------------------------------------------------------
// Persistent recurrent kernel (R12 verbatim — proven, no spills).
// 128 blocks x 512 threads; block bx owns hidden cols [bx*8, bx*8+8) across
// all 4 gates (32 w_hh rows) cached in SMEM; 4-way K-split, TM=4 x TN=4;
// h streamed via cp.async (8 chunks of 128 k, 2 buffers); c in register;
// R8-proven global barrier.
// ---------------------------------------------------------------------------
constexpr int WS_STRIDE = 1028;                    // 1024+4 words
constexpr int WS_SIZE   = 32 * WS_STRIDE;          // 32896 floats (131584 B)
constexpr int AS_STRIDE = 132;                     // 128+4 words (16B-aligned rows)
constexpr int AS_CHUNK  = 64 * AS_STRIDE;          // 8448 floats per buffer
constexpr int AS_SIZE   = 2 * AS_CHUNK;            // 16896 floats (67584 B)
constexpr int GB_HALF   = 64 * 33;                 // 2112 floats
// Gb (4 x 2112 = 8448 floats) overlays the As buffers (sync-separated).
constexpr size_t LP_SMEM = (size_t)(WS_SIZE + AS_SIZE) * 4;       // 199168 B

__global__ __launch_bounds__(512, 1) void lstm_persist(const float* __restrict__ w_hh,
                                                       const float* __restrict__ bias) {
    extern __shared__ float sm[];
    float* Ws = sm;                    // [32][1028]
    float* As = sm + WS_SIZE;          // [2][64][132]
    float* Gb = As;                    // overlay, [4][64][33]

    const int tid  = threadIdx.x;
    const int q    = tid >> 7;         // K-split quarter 0..3
    const int htid = tid & 127;
    const int tc   = htid & 7;         // local col base 0..7
    const int tr   = htid >> 3;        // batch row base 0..15
    const int j0   = blockIdx.x * 8;

    // pointwise mapping (fixed across steps -> c in register)
    const int pb = tid >> 3;           // batch 0..63
    const int pj = tid & 7;            // hidden col offset 0..7
    float c_reg = 0.0f;

    // ---- one-time: cache this block's 32 w_hh rows (full K) in SMEM ----
    for (int i = tid; i < 32 * 256; i += 512) {        // 8192 float4
        int row = i >> 8, qq = i & 255;
        int grow = (row >> 3) * HDIM + j0 + (row & 7); // gate*H + j0 + jj
        *reinterpret_cast<float4*>(Ws + row * WS_STRIDE + qq * 4) =
            *reinterpret_cast<const float4*>(w_hh + (size_t)grow * HDIM + qq * 4);
    }
    const uint32_t as_base = (uint32_t)__cvta_generic_to_shared(As);
    __syncthreads();

    for (int t = 0; t < TT; ++t) {
        const float* __restrict__ hin = (t & 1) ? g_h1 : g_h0;
        float* __restrict__ hout      = (t & 1) ? g_h0 : g_h1;

        // prefetch x_proj gate values (consumed ~8us later -> latency hidden)
        float xg[4];
        const float* xr = (t < ILEN) ? (g_xproj + ((size_t)pb * ILEN + t) * G4) : bias;
#pragma unroll
        for (int g = 0; g < 4; ++g) xg[g] = __ldg(xr + g * HDIM + j0 + pj);

        unsigned long long acc[4][4];
#pragma unroll
        for (int i = 0; i < 4; ++i)
#pragma unroll
            for (int j = 0; j < 4; ++j) acc[i][j] = 0ull;

        // h chunk streamer: 64 batch rows x 128 k  (2048 float4, 4/thread)
        auto issue = [&](int c, int buf) {
#pragma unroll
            for (int v = 0; v < 4; ++v) {
                int id = tid + v * 512;
                int r = id >> 5, q32 = id & 31;
                cp_async16(as_base + (uint32_t)((buf * AS_CHUNK + r * AS_STRIDE + q32 * 4) * 4),
                           hin + (size_t)r * HDIM + c * 128 + q32 * 4);
            }
        };

        issue(0, 0); cp_commit();

        for (int c = 0; c < 8; ++c) {
            cp_wait<0>();                // chunk c (sole pending group) complete
            __syncthreads();             // all warps done mac(c-1): buf (c+1)&1 free
            if (c < 7) { issue(c + 1, (c + 1) & 1); cp_commit(); }
            const float* Ap = As + (c & 1) * AS_CHUNK + q * 32;
            const float* Wp = Ws + c * 128 + q * 32;
            mac_g<4, 4, 8, AS_STRIDE, WS_STRIDE, 16, 8>(Ap, Wp, tr, tc, acc);
        }
        __syncthreads();                 // all mac done before Gb overlays As

        // dump K-split partials: Gb[q][batch][lcol], stride 33
        float* gb = Gb + q * GB_HALF;
#pragma unroll
        for (int i = 0; i < 4; ++i)
#pragma unroll
            for (int j = 0; j < 4; ++j)
                gb[(tr + 16 * i) * 33 + (tc + 8 * j)] = pair_sum(acc[i][j]);
        __syncthreads();

        // pointwise LSTM update: 512 elements, 1 per thread
        float pre[4];
#pragma unroll
        for (int g = 0; g < 4; ++g) {
            int off = pb * 33 + g * 8 + pj;
            pre[g] = xg[g] + Gb[off] + Gb[GB_HALF + off] +
                     Gb[2 * GB_HALF + off] + Gb[3 * GB_HALF + off];
        }
        float ig = sigmoidf_(pre[0]);
        float fg = sigmoidf_(pre[1]);
        float gg = tanhf(pre[2]);
        float og = sigmoidf_(pre[3]);
        float cn = fg * c_reg + ig * gg;
        c_reg = cn;
        float hn = og * tanhf(cn);
        int hidx = pb * HDIM + j0 + pj;
        hout[hidx] = hn;
        if (t >= ILEN)
            g_hs[(size_t)(t - ILEN) * (BSZ * HDIM) + hidx] = hn;

        // ---- grid barrier (R8-proven protocol, verbatim) ----
        __threadfence();
        __syncthreads();
        if (tid == 0) {
            atomicAdd(&g_arrive, 1u);
            unsigned target = (unsigned)NBLK * (unsigned)(t + 1);
            while (*(volatile unsigned*)&g_arrive < target) { }
        }
        __syncthreads();
        __threadfence();
    }
}

// ---------------------------------------------------------------------------
// classifier: out[b][tt][o] = sigmoid(hs_row . clf_w[o] + clf_b[o])
// rows = tt*64 + b. BM=64, BN=64, KC=64 (16 quads), TM=4, TN=4, stride 68.
// ---------------------------------------------------------------------------
__global__ __launch_bounds__(256) void clf_kernel(const float* __restrict__ clf_w,
                                                  const float* __restrict__ clf_b,
                                                  float* __restrict__ out) {
    constexpr int KC = 64, SKC = 68, TM = 4, TN = 4;
    __shared__ float As[64 * SKC];
    __shared__ float Bs[64 * SKC];
    const int tid = threadIdx.x;
    const int tr = tid >> 4, tc = tid & 15;
    const int row0 = blockIdx.y * 64;
    const int col0 = blockIdx.x * 64;

    unsigned long long acc[TM][TN];
#pragma unroll
    for (int i = 0; i < TM; ++i)
#pragma unroll
        for (int j = 0; j < TN; ++j) acc[i][j] = 0ull;

    for (int k0 = 0; k0 < HDIM; k0 += KC) {
#pragma unroll
        for (int v = 0; v < 4; ++v) {           // 64*16 = 1024 float4
            int id = tid + v * 256;
            int r = id >> 4, kq = id & 15;
            *reinterpret_cast<float4*>(As + r * SKC + kq * 4) =
                *reinterpret_cast<const float4*>(g_hs + (size_t)(row0 + r) * HDIM + k0 + kq * 4);
        }
#pragma unroll
        for (int v = 0; v < 4; ++v) {
            int id = tid + v * 256;
            int r = id >> 4, kq = id & 15;
            *reinterpret_cast<float4*>(Bs + r * SKC + kq * 4) =
                *reinterpret_cast<const float4*>(clf_w + (size_t)(col0 + r) * HDIM + k0 + kq * 4);
        }
        __syncthreads();
        mac_g<TM, TN, KC / 4, SKC, SKC, 16, 16>(As, Bs, tr, tc, acc);
        __syncthreads();
    }

#pragma unroll
    for (int j = 0; j < TN; ++j) {
        int o = col0 + tc + 16 * j;
        float bv = clf_b[o];
#pragma unroll
        for (int i = 0; i < TM; ++i) {
            int r  = row0 + tr + 16 * i;
            int tt = r >> 6;
            int b  = r & 63;
            out[((size_t)b * TLEN + tt) * ODIM + o] =
                1.0f / (1.0f + expf(-(pair_sum(acc[i][j]) + bv)));
        }
    }
}

// ---------------------------------------------------------------------------
// launch (graph-capturable: kernel launches only, default stream)
// Inputs (metadata order): inp, tlen, w_ih, w_hh, b, clf_w, clf_b
// ---------------------------------------------------------------------------
extern "C" void kernel_launch(void* const* d_in, const int* in_sizes, int n_in,
                              void* d_out, int out_size) {
    const float* inp   = (const float*)d_in[0];
    // d_in[1] = tlen (int32) — fixed at 64
    const float* w_ih  = (const float*)d_in[2];
    const float* w_hh  = (const float*)d_in[3];
    const float* bias  = (const float*)d_in[4];
    const float* clf_w = (const float*)d_in[5];
    const float* clf_b = (const float*)d_in[6];
    float* out = (float*)d_out;

    cudaFuncSetAttribute(xproj_kernel, cudaFuncAttributeMaxDynamicSharedMemorySize,
                         (int)XP_SMEM);
    cudaFuncSetAttribute(lstm_persist, cudaFuncAttributeMaxDynamicSharedMemorySize,
                         (int)LP_SMEM);

    init_kernel<<<(BSZ * HDIM + 255) / 256, 256>>>();
    xproj_kernel<<<dim3(G4 / 64, (BSZ * ILEN) / 64), 256, XP_SMEM>>>(inp, w_ih, bias);
    lstm_persist<<<NBLK, 512, LP_SMEM>>>(w_hh, bias);
    clf_kernel<<<dim3(ODIM / 64, (TLEN * BSZ) / 64), 256>>>(clf_w, clf_b, out);
}